// round 1
// baseline (speedup 1.0000x reference)
#include <cuda_runtime.h>

#define HH 128
#define WW 128

// Depthwise 4x4 blur (upfirdn2d pad=(2,1), up=down=1), separable rank-1 kernel.
// out[y][x] = sum_{i,j} x[y+i-2][x+j-2] * K[3-i][3-j]
// K[a][b] = r[a]*c[b]  (rank-1 by construction in the reference)
// => out = V-pass( H-pass(x, hk), vk ), hk[j]=c[3-j], vk[i]=r[3-i]
__global__ __launch_bounds__(256) void blur_kernel(
    const float* __restrict__ x,
    const float* __restrict__ ker,
    float* __restrict__ out)
{
    const int plane = blockIdx.y;                 // (n,c) plane, 2048 total
    const int y0 = blockIdx.x * 32 + threadIdx.y * 4;   // 4-row output block
    const int x0 = threadIdx.x * 4;                     // 4-col output block

    // ---- factorize 4x4 kernel (rank-1): c[b]=K[0][b], r[a]=K[a][0]/K[0][0]
    const float c0 = __ldg(ker + 0), c1 = __ldg(ker + 1);
    const float c2 = __ldg(ker + 2), c3 = __ldg(ker + 3);
    const float inv = 1.0f / c0;
    const float r1 = __ldg(ker + 4)  * inv;
    const float r2 = __ldg(ker + 8)  * inv;
    const float r3 = __ldg(ker + 12) * inv;
    // flipped taps
    const float hk0 = c3, hk1 = c2, hk2 = c1, hk3 = c0;
    const float vk0 = r3, vk1 = r2, vk2 = r1, vk3 = 1.0f;

    const float* __restrict__ p = x   + (size_t)plane * (HH * WW);
    float*       __restrict__ q = out + (size_t)plane * (HH * WW);

    float4 acc0 = make_float4(0.f, 0.f, 0.f, 0.f);
    float4 acc1 = acc0, acc2 = acc0, acc3 = acc0;

    const bool hasL = (x0 > 0);          // left halo in-bounds?
    const bool hasR = (x0 + 4 < WW);     // right halo in-bounds?

    #pragma unroll
    for (int rr = -2; rr <= 4; ++rr) {
        const int ri = y0 + rr;
        const bool rv = (ri >= 0) && (ri < HH);
        const float* row = p + ri * WW;

        float2 L = make_float2(0.f, 0.f);
        float4 M = make_float4(0.f, 0.f, 0.f, 0.f);
        float  R = 0.f;
        if (rv) {
            if (hasL) L = *reinterpret_cast<const float2*>(row + x0 - 2); // 8B-aligned
            M = *reinterpret_cast<const float4*>(row + x0);               // 16B-aligned
            if (hasR) R = row[x0 + 4];
        }

        // horizontal pass: h[x] = sum_j in[x-2+j]*hk[j]
        float4 h;
        h.x = fmaf(L.x, hk0, fmaf(L.y, hk1, fmaf(M.x, hk2, M.y * hk3)));
        h.y = fmaf(L.y, hk0, fmaf(M.x, hk1, fmaf(M.y, hk2, M.z * hk3)));
        h.z = fmaf(M.x, hk0, fmaf(M.y, hk1, fmaf(M.z, hk2, M.w * hk3)));
        h.w = fmaf(M.y, hk0, fmaf(M.z, hk1, fmaf(M.w, hk2, R   * hk3)));

        // vertical accumulate: out row o uses h rows (y0+o-2 .. y0+o+1),
        // this h row (rr) feeds o in [rr-1, rr+2] with weight vk[rr - o + 2]
        #pragma unroll
        for (int o = 0; o < 4; ++o) {
            const int i = rr - o + 2;
            if (i >= 0 && i <= 3) {
                const float v = (i == 0) ? vk0 : (i == 1) ? vk1 : (i == 2) ? vk2 : vk3;
                float4* a = (o == 0) ? &acc0 : (o == 1) ? &acc1 : (o == 2) ? &acc2 : &acc3;
                a->x = fmaf(h.x, v, a->x);
                a->y = fmaf(h.y, v, a->y);
                a->z = fmaf(h.z, v, a->z);
                a->w = fmaf(h.w, v, a->w);
            }
        }
    }

    *reinterpret_cast<float4*>(q + (y0 + 0) * WW + x0) = acc0;
    *reinterpret_cast<float4*>(q + (y0 + 1) * WW + x0) = acc1;
    *reinterpret_cast<float4*>(q + (y0 + 2) * WW + x0) = acc2;
    *reinterpret_cast<float4*>(q + (y0 + 3) * WW + x0) = acc3;
}

extern "C" void kernel_launch(void* const* d_in, const int* in_sizes, int n_in,
                              void* d_out, int out_size)
{
    const float* x   = (const float*)d_in[0];
    const float* ker = (const float*)d_in[1];
    float*       out = (float*)d_out;

    const int planes = in_sizes[0] / (HH * WW);   // 8*256 = 2048
    dim3 block(32, 8);            // 256 threads: 32 x-quads, 8 y-quads
    dim3 grid(HH / 32, planes);   // 4 y-tiles per plane
    blur_kernel<<<grid, block>>>(x, ker, out);
}